// round 8
// baseline (speedup 1.0000x reference)
#include <cuda_runtime.h>
#include <cuda_bf16.h>
#include <cuda_fp16.h>

// BoundaryLoss: loss = sum_{b,c,d,h,w} Gx(q)^2 + 2*Gy(q)^2 (normalized),
// q = softmax(pred, axis=C) - onehot(target); 2-D sobel per depth slice.
// pred (2,4,96,160,160) f32, target (2,96,160,160) i32.
// Persistent blocks; q staged in smem as fp16; sobel in packed half2;
// next-tile loads overlapped with current-tile sobel.

#define BB 2
#define CC 4
#define DD 96
#define HH 160
#define WW 160

#define TH 16                       // output rows per tile
#define HALO (TH + 2)               // 18
#define RTILES (HH / TH)            // 10
#define NTILE (BB * DD * RTILES)    // 1920
#define NPBLK 592                   // persistent blocks = 148 SMs x 4
#define NTHREADS 320
#define PITCHB 336                  // bytes/row: [4 guard][160 data][4 guard] halfs

#define CHSTR4 (DD * HH * WW / 4)

__device__ float g_partial[NPBLK];
__device__ int   g_count = 0;

__device__ __forceinline__ __half2 u2h(unsigned x) {
    return *reinterpret_cast<__half2*>(&x);
}
__device__ __forceinline__ unsigned h2u(__half2 x) {
    return *reinterpret_cast<unsigned*>(&x);
}

__global__ __launch_bounds__(NTHREADS, 4)
void bl_main_kernel(const float* __restrict__ pred,
                    const int*   __restrict__ target,
                    float*       __restrict__ out)
{
    __shared__ __align__(16) unsigned char qsm[CC * HALO * PITCHB];  // 24192 B
    __shared__ float warpsum[NTHREADS / 32];
    __shared__ double dwarpsum[NTHREADS / 32];
    __shared__ bool  is_last;

    const int tid  = threadIdx.x;
    const int j0   = tid / 40;            // 0..7
    const int vcol = tid - j0 * 40;       // 0..39
    const bool hasC = (tid < 80);         // threads owning halo rows 16,17

    // ---- guard halfs: zero [0..3] and [164..167] per (c,row); constant ----
    if (tid < CC * HALO * 2) {
        const int c    = tid / (HALO * 2);
        const int rem  = tid - c * (HALO * 2);
        const int row  = rem >> 1;
        const int side = rem & 1;
        *(uint2*)(qsm + (c * HALO + row) * PITCHB + (side ? 328 : 0)) = make_uint2(0u, 0u);
    }

    // phase-2 thread mapping: (class c2, 4-col group g2, 8-row strip s2)
    const int c2   = tid / 80;
    const int rem2 = tid - c2 * 80;
    const int s2   = rem2 / 40;
    const int g2   = rem2 - s2 * 40;
    const int off2 = 8 * g2;
    const unsigned char* rbase = qsm + (c2 * HALO + s2 * 8) * PITCHB;

    const float4 Z4 = make_float4(0.f, 0.f, 0.f, 0.f);
    const int4   ZT = make_int4(-1, -1, -1, -1);

    float axs = 0.f, ays = 0.f;

#define SOFTMAX_STORE(X0, X1, X2, X3, T, J)                                         \
    {                                                                               \
        float4 q0, q1, q2, q3;                                                      \
        {                                                                           \
            float e0 = __expf(X0.x), e1 = __expf(X1.x), e2 = __expf(X2.x), e3 = __expf(X3.x); \
            float r = __frcp_rn(e0 + e1 + e2 + e3);                                 \
            q0.x = e0 * r - (T.x == 0); q1.x = e1 * r - (T.x == 1);                 \
            q2.x = e2 * r - (T.x == 2); q3.x = e3 * r - (T.x == 3);                 \
        }                                                                           \
        {                                                                           \
            float e0 = __expf(X0.y), e1 = __expf(X1.y), e2 = __expf(X2.y), e3 = __expf(X3.y); \
            float r = __frcp_rn(e0 + e1 + e2 + e3);                                 \
            q0.y = e0 * r - (T.y == 0); q1.y = e1 * r - (T.y == 1);                 \
            q2.y = e2 * r - (T.y == 2); q3.y = e3 * r - (T.y == 3);                 \
        }                                                                           \
        {                                                                           \
            float e0 = __expf(X0.z), e1 = __expf(X1.z), e2 = __expf(X2.z), e3 = __expf(X3.z); \
            float r = __frcp_rn(e0 + e1 + e2 + e3);                                 \
            q0.z = e0 * r - (T.z == 0); q1.z = e1 * r - (T.z == 1);                 \
            q2.z = e2 * r - (T.z == 2); q3.z = e3 * r - (T.z == 3);                 \
        }                                                                           \
        {                                                                           \
            float e0 = __expf(X0.w), e1 = __expf(X1.w), e2 = __expf(X2.w), e3 = __expf(X3.w); \
            float r = __frcp_rn(e0 + e1 + e2 + e3);                                 \
            q0.w = e0 * r - (T.w == 0); q1.w = e1 * r - (T.w == 1);                 \
            q2.w = e2 * r - (T.w == 2); q3.w = e3 * r - (T.w == 3);                 \
        }                                                                           \
        const int bo_ = 8 + 8 * vcol + (J) * PITCHB;                                \
        *(uint2*)(qsm + 0 * HALO * PITCHB + bo_) =                                  \
            make_uint2(h2u(__floats2half2_rn(q0.x, q0.y)), h2u(__floats2half2_rn(q0.z, q0.w))); \
        *(uint2*)(qsm + 1 * HALO * PITCHB + bo_) =                                  \
            make_uint2(h2u(__floats2half2_rn(q1.x, q1.y)), h2u(__floats2half2_rn(q1.z, q1.w))); \
        *(uint2*)(qsm + 2 * HALO * PITCHB + bo_) =                                  \
            make_uint2(h2u(__floats2half2_rn(q2.x, q2.y)), h2u(__floats2half2_rn(q2.z, q2.w))); \
        *(uint2*)(qsm + 3 * HALO * PITCHB + bo_) =                                  \
            make_uint2(h2u(__floats2half2_rn(q3.x, q3.y)), h2u(__floats2half2_rn(q3.z, q3.w))); \
    }

#define ZERO_ROW(J)                                                                 \
    {                                                                               \
        const int bo_ = 8 + 8 * vcol + (J) * PITCHB;                                \
        const uint2 z = make_uint2(0u, 0u);                                         \
        *(uint2*)(qsm + 0 * HALO * PITCHB + bo_) = z;                               \
        *(uint2*)(qsm + 1 * HALO * PITCHB + bo_) = z;                               \
        *(uint2*)(qsm + 2 * HALO * PITCHB + bo_) = z;                               \
        *(uint2*)(qsm + 3 * HALO * PITCHB + bo_) = z;                               \
    }

#define LOAD_B(T_, B0, B1, B2, B3, TB)                                              \
    {                                                                               \
        const int slice_ = (T_) / RTILES;                                           \
        const int rt_    = (T_) - slice_ * RTILES;                                  \
        const int bI_    = slice_ / DD;                                             \
        const int dI_    = slice_ - bI_ * DD;                                       \
        const int hB_    = rt_ * TH + j0 + 7;       /* always in [7,158] */         \
        const float4* prB_ = (const float4*)(pred + (size_t)(bI_ * CC * DD + dI_) * (HH * WW)) \
                             + (size_t)hB_ * 40 + vcol;                             \
        B0 = prB_[0]; B1 = prB_[CHSTR4]; B2 = prB_[2 * CHSTR4]; B3 = prB_[3 * CHSTR4]; \
        TB = ((const int4*)(target + (size_t)slice_ * (HH * WW)))[hB_ * 40 + vcol]; \
    }

    int t = blockIdx.x;

    // ---- prologue: stage B(t) ----
    float4 b0, b1, b2, b3; int4 tb;
    LOAD_B(t, b0, b1, b2, b3, tb);

    while (true) {
        const int slice = t / RTILES;
        const int rt    = t - slice * RTILES;
        const int bI    = slice / DD;
        const int dI    = slice - bI * DD;
        const int h0    = rt * TH;
        const float* pred_bd = pred + (size_t)(bI * CC * DD + dI) * (HH * WW);
        const int*   tgt_bd  = target + (size_t)slice * (HH * WW);

        // ---- issue A and C loads (both in flight during B softmax) ----
        const bool vA = (h0 + j0) > 0;                 // row h0+j0-1 valid
        float4 a0 = Z4, a1 = Z4, a2 = Z4, a3 = Z4; int4 ta = ZT;
        if (vA) {
            const int hA = h0 + j0 - 1;
            const float4* prA = (const float4*)pred_bd + (size_t)hA * 40 + vcol;
            a0 = prA[0]; a1 = prA[CHSTR4]; a2 = prA[2 * CHSTR4]; a3 = prA[3 * CHSTR4];
            ta = ((const int4*)tgt_bd)[hA * 40 + vcol];
        }
        const bool vC = hasC && (h0 + 15 + j0 < HH);   // row h0+15+j0
        float4 c0 = Z4, c1 = Z4, c2v = Z4, c3 = Z4; int4 tc = ZT;
        if (vC) {
            const int hC = h0 + 15 + j0;
            const float4* prC = (const float4*)pred_bd + (size_t)hC * 40 + vcol;
            c0 = prC[0]; c1 = prC[CHSTR4]; c2v = prC[2 * CHSTR4]; c3 = prC[3 * CHSTR4];
            tc = ((const int4*)tgt_bd)[hC * 40 + vcol];
        }

        // ---- stores: B (staged) first, then A, then C ----
        SOFTMAX_STORE(b0, b1, b2, b3, tb, j0 + 8);
        if (vA) { SOFTMAX_STORE(a0, a1, a2, a3, ta, j0); } else { ZERO_ROW(j0); }
        if (hasC) {
            if (vC) { SOFTMAX_STORE(c0, c1, c2v, c3, tc, 16 + j0); }
            else    { ZERO_ROW(16 + j0); }
        }

        const int  tn   = t + NPBLK;
        const bool more = (tn < NTILE);
        __syncthreads();

        // ---- stage B(t+1): LDG in flight during the whole sobel below ----
        if (more) LOAD_B(tn, b0, b1, b2, b3, tb);

        // ---- phase 2: separable sobel in packed half2 ----
        {
            const __half2 TWOH = __half2half2(__float2half(2.0f));
            const __half2 ZERO = __half2half2(__float2half(0.0f));
            const unsigned char* rp = rbase;

            __half2 pu[2], pv[2], cu[2], cv[2];

#define ROW_UV(RP, U, V)                                                  \
    {                                                                     \
        const unsigned eL = *(const unsigned*)((RP) + 4 + off2);          \
        const uint2    M  = *(const uint2*)((RP) + 8 + off2);             \
        const unsigned eR = *(const unsigned*)((RP) + 16 + off2);         \
        const __half2 S0 = u2h(__byte_perm(eL, M.x, 0x5432));             \
        const __half2 S1 = u2h(__byte_perm(M.x, M.y, 0x5432));            \
        const __half2 S2 = u2h(__byte_perm(M.y, eR, 0x5432));             \
        U[0] = __hfma2(u2h(M.x), TWOH, __hadd2(S0, S1));                  \
        U[1] = __hfma2(u2h(M.y), TWOH, __hadd2(S1, S2));                  \
        V[0] = __hsub2(S1, S0);                                           \
        V[1] = __hsub2(S2, S1);                                           \
    }

            ROW_UV(rp, pu, pv); rp += PITCHB;
            ROW_UV(rp, cu, cv); rp += PITCHB;

#pragma unroll
            for (int half_blk = 0; half_blk < 2; half_blk++) {
                __half2 axh = ZERO, ayh = ZERO;
#pragma unroll
                for (int k = 0; k < 4; k++) {
                    __half2 nu[2], nv[2];
                    ROW_UV(rp, nu, nv); rp += PITCHB;
#pragma unroll
                    for (int i = 0; i < 2; i++) {
                        const __half2 gx = __hfma2(cv[i], TWOH, __hadd2(pv[i], nv[i]));
                        const __half2 gy = __hsub2(nu[i], pu[i]);
                        axh = __hfma2(gx, gx, axh);
                        ayh = __hfma2(gy, gy, ayh);
                        pu[i] = cu[i]; pv[i] = cv[i];
                        cu[i] = nu[i]; cv[i] = nv[i];
                    }
                }
                const float2 fx = __half22float2(axh);
                const float2 fy = __half22float2(ayh);
                axs += fx.x + fx.y;
                ays += fy.x + fy.y;
            }
#undef ROW_UV
        }

        __syncthreads();            // sobel reads done before next tile's stores
        if (!more) break;
        t = tn;
    }

    float acc = axs + 2.f * ays;

    // ---- block reduction -> per-block partial (once per block) ----
#pragma unroll
    for (int o = 16; o > 0; o >>= 1)
        acc += __shfl_down_sync(0xffffffffu, acc, o);
    if ((tid & 31) == 0) warpsum[tid >> 5] = acc;
    __syncthreads();

    if (tid == 0) {
        float sm = 0.f;
#pragma unroll
        for (int i = 0; i < NTHREADS / 32; i++) sm += warpsum[i];
        g_partial[blockIdx.x] = sm;
        __threadfence();
        is_last = (atomicAdd(&g_count, 1) == NPBLK - 1);
    }
    __syncthreads();

    // ---- last block: final reduction + output + counter reset ----
    if (is_last) {
        double sd = 0.0;
        for (int i = tid; i < NPBLK; i += NTHREADS) sd += (double)g_partial[i];
#pragma unroll
        for (int o = 16; o > 0; o >>= 1)
            sd += __shfl_down_sync(0xffffffffu, sd, o);
        if ((tid & 31) == 0) dwarpsum[tid >> 5] = sd;
        __syncthreads();
        if (tid == 0) {
            double tot = 0.0;
#pragma unroll
            for (int i = 0; i < NTHREADS / 32; i++) tot += dwarpsum[i];
            const double per_tensor = (double)BB * (DD + 2) * (HH + 2) * (WW + 2);
            out[0] = (float)(tot / per_tensor / (double)CC);
            g_count = 0;
        }
    }

#undef SOFTMAX_STORE
#undef ZERO_ROW
#undef LOAD_B
}

extern "C" void kernel_launch(void* const* d_in, const int* in_sizes, int n_in,
                              void* d_out, int out_size)
{
    const float* pred   = (const float*)d_in[0];
    const int*   target = (const int*)d_in[1];
    float*       out    = (float*)d_out;

    bl_main_kernel<<<NPBLK, NTHREADS>>>(pred, target, out);
}

// round 9
// speedup vs baseline: 1.6070x; 1.6070x over previous
#include <cuda_runtime.h>
#include <cuda_bf16.h>
#include <cuda_fp16.h>

// BoundaryLoss: loss = sum_{b,c,d,h,w} Gx(q)^2 + 2*Gy(q)^2 (normalized),
// q = softmax(pred, axis=C) - onehot(target); 2-D sobel per depth slice.
// pred (2,4,96,160,160) f32, target (2,96,160,160) i32.
// TH=32 tiles, 640-thread blocks (2/SM); q in smem as fp16; half2 sobel.

#define BB 2
#define CC 4
#define DD 96
#define HH 160
#define WW 160

#define TH 32                       // output rows per block
#define HALO (TH + 2)               // 34
#define RTILES (HH / TH)            // 5
#define NBLK (BB * DD * RTILES)     // 960
#define NTHREADS 640
#define NWARP (NTHREADS / 32)       // 20
#define PITCHB 336                  // bytes/row: [4 guard][160 data][4 guard] halfs

#define CHSTR4 (DD * HH * WW / 4)

__device__ float g_partial[NBLK];
__device__ int   g_count = 0;

__device__ __forceinline__ __half2 u2h(unsigned x) {
    return *reinterpret_cast<__half2*>(&x);
}
__device__ __forceinline__ unsigned h2u(__half2 x) {
    return *reinterpret_cast<unsigned*>(&x);
}

__global__ __launch_bounds__(NTHREADS, 2)
void bl_main_kernel(const float* __restrict__ pred,
                    const int*   __restrict__ target,
                    float*       __restrict__ out)
{
    __shared__ __align__(16) unsigned char qsm[CC * HALO * PITCHB];  // 45696 B
    __shared__ float warpsum[NWARP];
    __shared__ double dwarpsum[NWARP];
    __shared__ bool  is_last;

    const int blk   = blockIdx.x;
    const int rt    = blk % RTILES;
    const int slice = blk / RTILES;
    const int b     = slice / DD;
    const int d     = slice - b * DD;
    const int h0    = rt * TH;

    const float* pred_bd = pred + (size_t)(b * CC * DD + d) * (HH * WW);
    const int*   tgt_bd  = target + (size_t)slice * (HH * WW);

    const int tid = threadIdx.x;

    // ---- guard halfs: zero [0..3] and [164..167] per (c,row) ----
    if (tid < CC * HALO * 2) {
        const int c    = tid / (HALO * 2);
        const int rem  = tid - c * (HALO * 2);
        const int row  = rem >> 1;
        const int side = rem & 1;
        *(uint2*)(qsm + (c * HALO + row) * PITCHB + (side ? 328 : 0)) = make_uint2(0u, 0u);
    }

#define SOFTMAX_STORE(X0, X1, X2, X3, T, J, VC)                                     \
    {                                                                               \
        float4 q0, q1, q2, q3;                                                      \
        {                                                                           \
            float e0 = __expf(X0.x), e1 = __expf(X1.x), e2 = __expf(X2.x), e3 = __expf(X3.x); \
            float r = __frcp_rn(e0 + e1 + e2 + e3);                                 \
            q0.x = e0 * r - (T.x == 0); q1.x = e1 * r - (T.x == 1);                 \
            q2.x = e2 * r - (T.x == 2); q3.x = e3 * r - (T.x == 3);                 \
        }                                                                           \
        {                                                                           \
            float e0 = __expf(X0.y), e1 = __expf(X1.y), e2 = __expf(X2.y), e3 = __expf(X3.y); \
            float r = __frcp_rn(e0 + e1 + e2 + e3);                                 \
            q0.y = e0 * r - (T.y == 0); q1.y = e1 * r - (T.y == 1);                 \
            q2.y = e2 * r - (T.y == 2); q3.y = e3 * r - (T.y == 3);                 \
        }                                                                           \
        {                                                                           \
            float e0 = __expf(X0.z), e1 = __expf(X1.z), e2 = __expf(X2.z), e3 = __expf(X3.z); \
            float r = __frcp_rn(e0 + e1 + e2 + e3);                                 \
            q0.z = e0 * r - (T.z == 0); q1.z = e1 * r - (T.z == 1);                 \
            q2.z = e2 * r - (T.z == 2); q3.z = e3 * r - (T.z == 3);                 \
        }                                                                           \
        {                                                                           \
            float e0 = __expf(X0.w), e1 = __expf(X1.w), e2 = __expf(X2.w), e3 = __expf(X3.w); \
            float r = __frcp_rn(e0 + e1 + e2 + e3);                                 \
            q0.w = e0 * r - (T.w == 0); q1.w = e1 * r - (T.w == 1);                 \
            q2.w = e2 * r - (T.w == 2); q3.w = e3 * r - (T.w == 3);                 \
        }                                                                           \
        const int bo_ = 8 + 8 * (VC) + (J) * PITCHB;                                \
        *(uint2*)(qsm + 0 * HALO * PITCHB + bo_) =                                  \
            make_uint2(h2u(__floats2half2_rn(q0.x, q0.y)), h2u(__floats2half2_rn(q0.z, q0.w))); \
        *(uint2*)(qsm + 1 * HALO * PITCHB + bo_) =                                  \
            make_uint2(h2u(__floats2half2_rn(q1.x, q1.y)), h2u(__floats2half2_rn(q1.z, q1.w))); \
        *(uint2*)(qsm + 2 * HALO * PITCHB + bo_) =                                  \
            make_uint2(h2u(__floats2half2_rn(q2.x, q2.y)), h2u(__floats2half2_rn(q2.z, q2.w))); \
        *(uint2*)(qsm + 3 * HALO * PITCHB + bo_) =                                  \
            make_uint2(h2u(__floats2half2_rn(q3.x, q3.y)), h2u(__floats2half2_rn(q3.z, q3.w))); \
    }

#define ZERO_ROW(J, VC)                                                             \
    {                                                                               \
        const int bo_ = 8 + 8 * (VC) + (J) * PITCHB;                                \
        const uint2 z = make_uint2(0u, 0u);                                         \
        *(uint2*)(qsm + 0 * HALO * PITCHB + bo_) = z;                               \
        *(uint2*)(qsm + 1 * HALO * PITCHB + bo_) = z;                               \
        *(uint2*)(qsm + 2 * HALO * PITCHB + bo_) = z;                               \
        *(uint2*)(qsm + 3 * HALO * PITCHB + bo_) = z;                               \
    }

    // ---- Phase 1: 3 rounds over 34 rows x 40 float4-cols (1360 items) ----
    const int j0 = tid / 40;            // 0..15
    const int vc = tid - j0 * 40;       // 0..39

    // Round 1: halo row j0, global row h0 + j0 - 1 (invalid only rt==0, j0==0)
    {
        const int h = h0 + j0 - 1;
        if (h >= 0) {
            const float4* pr = (const float4*)pred_bd + (size_t)h * 40 + vc;
            const float4 x0 = pr[0];
            const float4 x1 = pr[CHSTR4];
            const float4 x2 = pr[2 * CHSTR4];
            const float4 x3 = pr[3 * CHSTR4];
            const int4   t  = ((const int4*)tgt_bd)[h * 40 + vc];
            SOFTMAX_STORE(x0, x1, x2, x3, t, j0, vc);
        } else {
            ZERO_ROW(j0, vc);
        }
    }

    // Round 2: halo row j0+16, global row h0 + j0 + 15 — ALWAYS valid
    {
        const int h = h0 + j0 + 15;     // in [15, 158]
        const float4* pr = (const float4*)pred_bd + (size_t)h * 40 + vc;
        const float4 x0 = pr[0];
        const float4 x1 = pr[CHSTR4];
        const float4 x2 = pr[2 * CHSTR4];
        const float4 x3 = pr[3 * CHSTR4];
        const int4   t  = ((const int4*)tgt_bd)[h * 40 + vc];
        SOFTMAX_STORE(x0, x1, x2, x3, t, j0 + 16, vc);
    }

    // Round 3: ragged tail — halo rows 32,33 handled by tid < 80
    if (tid < 80) {
        const int j = 32 + (tid >= 40 ? 1 : 0);
        const int v = tid - (tid >= 40 ? 40 : 0);
        const int h = h0 + j - 1;       // h0+31 (always valid) or h0+32
        if (h < HH) {
            const float4* pr = (const float4*)pred_bd + (size_t)h * 40 + v;
            const float4 x0 = pr[0];
            const float4 x1 = pr[CHSTR4];
            const float4 x2 = pr[2 * CHSTR4];
            const float4 x3 = pr[3 * CHSTR4];
            const int4   t  = ((const int4*)tgt_bd)[h * 40 + v];
            SOFTMAX_STORE(x0, x1, x2, x3, t, j, v);
        } else {
            ZERO_ROW(j, v);
        }
    }
#undef SOFTMAX_STORE
#undef ZERO_ROW
    __syncthreads();

    // ---- Phase 2: separable sobel in packed half2 ----
    // thread -> (class c2, 4-col group g2, 8-row strip s2); 4*40*4 = 640
    const int c2   = tid / 160;
    const int rem2 = tid - c2 * 160;
    const int s2   = rem2 / 40;
    const int g2   = rem2 - s2 * 40;
    const int off2 = 8 * g2;

    const __half2 TWOH = __half2half2(__float2half(2.0f));
    const __half2 ZERO = __half2half2(__float2half(0.0f));
    const unsigned char* rp = qsm + (c2 * HALO + s2 * 8) * PITCHB;

    __half2 pu[2], pv[2], cu[2], cv[2];

#define ROW_UV(RP, U, V)                                                  \
    {                                                                     \
        const unsigned eL = *(const unsigned*)((RP) + 4 + off2);          \
        const uint2    M  = *(const uint2*)((RP) + 8 + off2);             \
        const unsigned eR = *(const unsigned*)((RP) + 16 + off2);         \
        const __half2 S0 = u2h(__byte_perm(eL, M.x, 0x5432));             \
        const __half2 S1 = u2h(__byte_perm(M.x, M.y, 0x5432));            \
        const __half2 S2 = u2h(__byte_perm(M.y, eR, 0x5432));             \
        U[0] = __hfma2(u2h(M.x), TWOH, __hadd2(S0, S1));                  \
        U[1] = __hfma2(u2h(M.y), TWOH, __hadd2(S1, S2));                  \
        V[0] = __hsub2(S1, S0);                                           \
        V[1] = __hsub2(S2, S1);                                           \
    }

    ROW_UV(rp, pu, pv); rp += PITCHB;
    ROW_UV(rp, cu, cv); rp += PITCHB;

    float ax = 0.f, ay = 0.f;
#pragma unroll
    for (int half_blk = 0; half_blk < 2; half_blk++) {
        __half2 axh = ZERO, ayh = ZERO;
#pragma unroll
        for (int k = 0; k < 4; k++) {
            __half2 nu[2], nv[2];
            ROW_UV(rp, nu, nv); rp += PITCHB;
#pragma unroll
            for (int i = 0; i < 2; i++) {
                const __half2 gx = __hfma2(cv[i], TWOH, __hadd2(pv[i], nv[i]));
                const __half2 gy = __hsub2(nu[i], pu[i]);
                axh = __hfma2(gx, gx, axh);
                ayh = __hfma2(gy, gy, ayh);
                pu[i] = cu[i]; pv[i] = cv[i];
                cu[i] = nu[i]; cv[i] = nv[i];
            }
        }
        const float2 fx = __half22float2(axh);
        const float2 fy = __half22float2(ayh);
        ax += fx.x + fx.y;
        ay += fy.x + fy.y;
    }
#undef ROW_UV

    float acc = ax + 2.f * ay;

    // ---- block reduction -> per-block partial ----
#pragma unroll
    for (int o = 16; o > 0; o >>= 1)
        acc += __shfl_down_sync(0xffffffffu, acc, o);
    if ((tid & 31) == 0) warpsum[tid >> 5] = acc;
    __syncthreads();

    if (tid == 0) {
        float sm = 0.f;
#pragma unroll
        for (int i = 0; i < NWARP; i++) sm += warpsum[i];
        g_partial[blk] = sm;
        __threadfence();
        is_last = (atomicAdd(&g_count, 1) == NBLK - 1);
    }
    __syncthreads();

    // ---- last block: final reduction + output + counter reset ----
    if (is_last) {
        double sd = 0.0;
        for (int i = tid; i < NBLK; i += NTHREADS) sd += (double)g_partial[i];
#pragma unroll
        for (int o = 16; o > 0; o >>= 1)
            sd += __shfl_down_sync(0xffffffffu, sd, o);
        if ((tid & 31) == 0) dwarpsum[tid >> 5] = sd;
        __syncthreads();
        if (tid == 0) {
            double tot = 0.0;
#pragma unroll
            for (int i = 0; i < NWARP; i++) tot += dwarpsum[i];
            const double per_tensor = (double)BB * (DD + 2) * (HH + 2) * (WW + 2);
            out[0] = (float)(tot / per_tensor / (double)CC);
            g_count = 0;
        }
    }
}

extern "C" void kernel_launch(void* const* d_in, const int* in_sizes, int n_in,
                              void* d_out, int out_size)
{
    const float* pred   = (const float*)d_in[0];
    const int*   target = (const int*)d_in[1];
    float*       out    = (float*)d_out;

    bl_main_kernel<<<NBLK, NTHREADS>>>(pred, target, out);
}